// round 1
// baseline (speedup 1.0000x reference)
#include <cuda_runtime.h>
#include <cstdint>
#include <cstddef>

// Problem constants
#define T_STEPS 1024
#define BATCH   128
#define M_ROWS  (BATCH * T_STEPS)   // 131072

// Scratch (allocation-free rule: __device__ globals)
__device__ float g_z[104857600];   // [131072, 800] max   (419 MB)
__device__ float g_ha[26214400];   // [131072, 200] max   (105 MB)
__device__ float g_hb[26214400];   // [131072, 200] max   (105 MB)

// ---------------------------------------------------------------- helpers
__device__ __forceinline__ float fast_tanh(float x) {
    float y;
    asm("tanh.approx.f32 %0, %1;" : "=f"(y) : "f"(x));
    return y;
}
__device__ __forceinline__ float fast_sig(float x) {
    return fmaf(fast_tanh(0.5f * x), 0.5f, 0.5f);
}
__device__ __forceinline__ uint32_t smem_u32(const void* p) {
    uint32_t a;
    asm("{ .reg .u64 t; cvta.to.shared.u64 t, %1; cvt.u32.u64 %0, t; }" : "=r"(a) : "l"(p));
    return a;
}

// ---------------------------------------------------------------- GEMM
// C[M,N] = A[M,K] @ B[K,N] + bias[N].  BM=BN=64, BK=16, 256 thr, 4x4 tiles.
__global__ __launch_bounds__(256) void sgemm_bias(
    const float* __restrict__ A, const float* __restrict__ B,
    const float* __restrict__ bias, float* __restrict__ C,
    int M, int N, int K)
{
    __shared__ float As[16][68];   // [k][m], padded
    __shared__ float Bs[16][64];   // [k][n]

    const int tid = threadIdx.x;
    const int tx = tid & 15, ty = tid >> 4;
    const int m0 = blockIdx.y * 64, n0 = blockIdx.x * 64;
    const int a_m = tid >> 4, a_k = tid & 15;   // A loader: 16 rows/pass
    const int b_k = tid >> 6, b_n = tid & 63;   // B loader: 4 k/pass

    float acc[4][4];
#pragma unroll
    for (int i = 0; i < 4; i++)
#pragma unroll
        for (int j = 0; j < 4; j++) acc[i][j] = 0.f;

    for (int k0 = 0; k0 < K; k0 += 16) {
#pragma unroll
        for (int i = 0; i < 4; i++) {
            int m = a_m + 16 * i;
            int kk = k0 + a_k;
            float v = 0.f;
            if (kk < K) v = A[(size_t)(m0 + m) * K + kk];
            As[a_k][m] = v;
        }
#pragma unroll
        for (int i = 0; i < 4; i++) {
            int kk = b_k + 4 * i;
            int gk = k0 + kk;
            int gn = n0 + b_n;
            float v = 0.f;
            if (gk < K && gn < N) v = B[(size_t)gk * N + gn];
            Bs[kk][b_n] = v;
        }
        __syncthreads();
#pragma unroll
        for (int kk = 0; kk < 16; kk++) {
            float4 a4 = *(const float4*)&As[kk][ty * 4];
            float4 b4 = *(const float4*)&Bs[kk][tx * 4];
            float a[4] = {a4.x, a4.y, a4.z, a4.w};
            float b[4] = {b4.x, b4.y, b4.z, b4.w};
#pragma unroll
            for (int i = 0; i < 4; i++)
#pragma unroll
                for (int j = 0; j < 4; j++)
                    acc[i][j] = fmaf(a[i], b[j], acc[i][j]);
        }
        __syncthreads();
    }

#pragma unroll
    for (int i = 0; i < 4; i++) {
        int m = m0 + ty * 4 + i;
#pragma unroll
        for (int j = 0; j < 4; j++) {
            int n = n0 + tx * 4 + j;
            if (n < N) C[(size_t)m * N + n] = acc[i][j] + bias[n];
        }
    }
}

// ---------------------------------------------------------------- scan H=100
// 128 CTAs, one batch row each. Wh (100x400, fp32) transposed in smem.
// Thread m (<100) owns h-index m: computes all 4 gate dots, updates c,h.
#define S1_KP 108                       // padded K stride (conflict-free LDS.128)
#define S1_SMEM ((400 * S1_KP + 2 * 104) * 4)

__global__ __launch_bounds__(128) void lstm_scan_h100(
    const float* __restrict__ Z, const float* __restrict__ Wh,
    float* __restrict__ Hout)
{
    extern __shared__ float sm[];
    float* whT = sm;                    // [400][S1_KP]  (col-major-ish, [col][k])
    float* hb  = sm + 400 * S1_KP;      // [2][104] double-buffered h

    const int tid = threadIdx.x;
    for (int idx = tid; idx < 100 * 400; idx += 128) {
        int k = idx / 400, cc = idx - k * 400;
        whT[cc * S1_KP + k] = Wh[idx];
    }
    if (tid < 104) { hb[tid] = 0.f; hb[104 + tid] = 0.f; }
    __syncthreads();

    const int row = blockIdx.x;
    const float* Zr = Z + (size_t)row * T_STEPS * 400;
    float* Ho = Hout + (size_t)row * T_STEPS * 100;
    const bool act = tid < 100;
    const int m = act ? tid : 0;

    const float4* wi = (const float4*)(whT + (      m) * S1_KP);
    const float4* wf = (const float4*)(whT + (100 + m) * S1_KP);
    const float4* wg = (const float4*)(whT + (200 + m) * S1_KP);
    const float4* wo = (const float4*)(whT + (300 + m) * S1_KP);

    float c = 0.f;
    int cur = 0;
    for (int t = 0; t < T_STEPS; t++) {
        float zi = 0.f, zf = 0.f, zg = 0.f, zo = 0.f;
        if (act) {
            const float* zp = Zr + (size_t)t * 400 + m;
            zi = zp[0]; zf = zp[100]; zg = zp[200]; zo = zp[300];
        }
        float ai0 = 0.f, ai1 = 0.f, af0 = 0.f, af1 = 0.f;
        float ag0 = 0.f, ag1 = 0.f, ao0 = 0.f, ao1 = 0.f;
        const float4* h4p = (const float4*)(hb + cur * 104);
        if (act) {
#pragma unroll
            for (int q = 0; q < 25; q++) {
                float4 h4 = h4p[q];
                float4 w;
                w = wi[q];
                ai0 = fmaf(h4.x, w.x, ai0); ai1 = fmaf(h4.y, w.y, ai1);
                ai0 = fmaf(h4.z, w.z, ai0); ai1 = fmaf(h4.w, w.w, ai1);
                w = wf[q];
                af0 = fmaf(h4.x, w.x, af0); af1 = fmaf(h4.y, w.y, af1);
                af0 = fmaf(h4.z, w.z, af0); af1 = fmaf(h4.w, w.w, af1);
                w = wg[q];
                ag0 = fmaf(h4.x, w.x, ag0); ag1 = fmaf(h4.y, w.y, ag1);
                ag0 = fmaf(h4.z, w.z, ag0); ag1 = fmaf(h4.w, w.w, ag1);
                w = wo[q];
                ao0 = fmaf(h4.x, w.x, ao0); ao1 = fmaf(h4.y, w.y, ao1);
                ao0 = fmaf(h4.z, w.z, ao0); ao1 = fmaf(h4.w, w.w, ao1);
            }
        }
        float hnew = 0.f;
        if (act) {
            float gi = fast_sig(zi + ai0 + ai1);
            float gf = fast_sig(zf + af0 + af1);
            float gg = fast_tanh(zg + ag0 + ag1);
            float go = fast_sig(zo + ao0 + ao1);
            c = fmaf(gf, c, gi * gg);
            hnew = go * fast_tanh(c);
            Ho[(size_t)t * 100 + m] = hnew;
        }
        int nxt = cur ^ 1;
        if (tid < 104) hb[nxt * 104 + tid] = hnew;   // pad lanes write 0
        __syncthreads();
        cur = nxt;
    }
}

// ---------------------------------------------------------------- scan H=200
// Cluster of 4 CTAs; CTA rank rk holds Wh columns for h-slice [50rk,50rk+50)
// (4 gate strips of 50 cols), fp32, 163 KB smem. 32 clusters x 4 batch rows.
// Thread tid<200: r=tid/50 (batch row in cluster), m=tid%50 (h idx in slice).
// Per step: full-h dot from local smem copy, gate update, then broadcast the
// new h slice to all 4 CTAs' next-buffer via mapa + st.shared::cluster, then
// one cluster barrier.
#define S2_KP 204
#define S2_WHF (200 * S2_KP)                 // whT floats
#define S2_SMEM ((S2_WHF + 2 * 4 * 200) * 4)

__global__ __launch_bounds__(256) void lstm_scan_h200(
    const float* __restrict__ Z, const float* __restrict__ Wh,
    float* __restrict__ Hout)
{
    extern __shared__ float sm[];
    float* whT = sm;                 // [200 local cols][S2_KP]
    float* hb  = sm + S2_WHF;        // [2][4][200]

    const int tid = threadIdx.x;
    uint32_t rk;
    asm("mov.u32 %0, %%cluster_ctarank;" : "=r"(rk));

    for (int idx = tid; idx < 200 * 200; idx += 256) {
        int k = idx / 200, lc = idx - k * 200;
        int g = lc / 50, mm = lc - g * 50;
        int gcol = g * 200 + (int)rk * 50 + mm;
        whT[lc * S2_KP + k] = Wh[k * 800 + gcol];
    }
    for (int i = tid; i < 2 * 4 * 200; i += 256) hb[i] = 0.f;
    __syncthreads();
    asm volatile("barrier.cluster.arrive.aligned;" ::: "memory");
    asm volatile("barrier.cluster.wait.aligned;" ::: "memory");

    const int b0 = (blockIdx.x >> 2) * 4;
    const bool act = tid < 200;
    const int r = act ? (tid / 50) : 0;
    const int m = act ? (tid - r * 50) : 0;
    const int gm = (int)rk * 50 + m;

    const float* Zr = Z + ((size_t)(b0 + r) * T_STEPS) * 800;
    float* Ho = Hout + ((size_t)(b0 + r) * T_STEPS) * 200;

    const float4* wi = (const float4*)(whT + (      m) * S2_KP);
    const float4* wf = (const float4*)(whT + ( 50 + m) * S2_KP);
    const float4* wg = (const float4*)(whT + (100 + m) * S2_KP);
    const float4* wo = (const float4*)(whT + (150 + m) * S2_KP);

    const uint32_t hb_base = smem_u32(hb);
    float c = 0.f;
    int cur = 0;
    for (int t = 0; t < T_STEPS; t++) {
        float zi = 0.f, zf = 0.f, zg = 0.f, zo = 0.f;
        if (act) {
            const float* zp = Zr + (size_t)t * 800 + gm;
            zi = zp[0]; zf = zp[200]; zg = zp[400]; zo = zp[600];
        }
        float ai0 = 0.f, ai1 = 0.f, af0 = 0.f, af1 = 0.f;
        float ag0 = 0.f, ag1 = 0.f, ao0 = 0.f, ao1 = 0.f;
        const float4* h4p = (const float4*)(hb + cur * 800 + r * 200);
        if (act) {
#pragma unroll 10
            for (int q = 0; q < 50; q++) {
                float4 h4 = h4p[q];
                float4 w;
                w = wi[q];
                ai0 = fmaf(h4.x, w.x, ai0); ai1 = fmaf(h4.y, w.y, ai1);
                ai0 = fmaf(h4.z, w.z, ai0); ai1 = fmaf(h4.w, w.w, ai1);
                w = wf[q];
                af0 = fmaf(h4.x, w.x, af0); af1 = fmaf(h4.y, w.y, af1);
                af0 = fmaf(h4.z, w.z, af0); af1 = fmaf(h4.w, w.w, af1);
                w = wg[q];
                ag0 = fmaf(h4.x, w.x, ag0); ag1 = fmaf(h4.y, w.y, ag1);
                ag0 = fmaf(h4.z, w.z, ag0); ag1 = fmaf(h4.w, w.w, ag1);
                w = wo[q];
                ao0 = fmaf(h4.x, w.x, ao0); ao1 = fmaf(h4.y, w.y, ao1);
                ao0 = fmaf(h4.z, w.z, ao0); ao1 = fmaf(h4.w, w.w, ao1);
            }
        }
        int nxt = cur ^ 1;
        if (act) {
            float gi = fast_sig(zi + ai0 + ai1);
            float gf = fast_sig(zf + af0 + af1);
            float gg = fast_tanh(zg + ag0 + ag1);
            float go = fast_sig(zo + ao0 + ao1);
            c = fmaf(gf, c, gi * gg);
            float hnew = go * fast_tanh(c);
            Ho[(size_t)t * 200 + gm] = hnew;
            // broadcast new h element into all 4 CTAs' next buffer
            uint32_t loff = hb_base + (uint32_t)((nxt * 800 + r * 200 + gm) * 4);
#pragma unroll
            for (uint32_t j = 0; j < 4; j++) {
                uint32_t pa;
                asm("mapa.shared::cluster.u32 %0, %1, %2;" : "=r"(pa) : "r"(loff), "r"(j));
                asm volatile("st.shared::cluster.f32 [%0], %1;" :: "r"(pa), "f"(hnew) : "memory");
            }
        }
        asm volatile("barrier.cluster.arrive.aligned;" ::: "memory");
        asm volatile("barrier.cluster.wait.aligned;" ::: "memory");
        cur = nxt;
    }
}

// ---------------------------------------------------------------- dense out
__global__ __launch_bounds__(256) void dense_out(
    const float* __restrict__ Hlast, const float* __restrict__ Wd,
    const float* __restrict__ bd, float* __restrict__ out)
{
    int p = blockIdx.x * blockDim.x + threadIdx.x;
    if (p >= BATCH * 6) return;
    int b = p / 6, o = p - b * 6;
    const float* h = Hlast + ((size_t)b * T_STEPS + (T_STEPS - 1)) * 200;
    float s = bd[o];
#pragma unroll 4
    for (int k = 0; k < 200; k++) s = fmaf(h[k], Wd[k * 6 + o], s);
    out[p] = s;
}

// ---------------------------------------------------------------- launch
static void launch_scan_big(const float* Z, const float* Wh, float* Hout)
{
    cudaFuncSetAttribute(lstm_scan_h200,
                         cudaFuncAttributeMaxDynamicSharedMemorySize, S2_SMEM);
    cudaLaunchConfig_t cfg = {};
    cfg.gridDim = dim3(128, 1, 1);
    cfg.blockDim = dim3(256, 1, 1);
    cfg.dynamicSmemBytes = S2_SMEM;
    cfg.stream = 0;
    cudaLaunchAttribute attrs[1];
    attrs[0].id = cudaLaunchAttributeClusterDimension;
    attrs[0].val.clusterDim.x = 4;
    attrs[0].val.clusterDim.y = 1;
    attrs[0].val.clusterDim.z = 1;
    cfg.attrs = attrs;
    cfg.numAttrs = 1;
    cudaLaunchKernelEx(&cfg, lstm_scan_h200, Z, Wh, Hout);
}

extern "C" void kernel_launch(void* const* d_in, const int* in_sizes, int n_in,
                              void* d_out, int out_size)
{
    const float* xs  = (const float*)d_in[0];
    const float* Wx0 = (const float*)d_in[1];
    const float* Wh0 = (const float*)d_in[2];
    const float* b0  = (const float*)d_in[3];
    const float* Wx1 = (const float*)d_in[4];
    const float* Wh1 = (const float*)d_in[5];
    const float* b1  = (const float*)d_in[6];
    const float* Wx2 = (const float*)d_in[7];
    const float* Wh2 = (const float*)d_in[8];
    const float* b2  = (const float*)d_in[9];
    const float* Wx3 = (const float*)d_in[10];
    const float* Wh3 = (const float*)d_in[11];
    const float* b3  = (const float*)d_in[12];
    const float* Wd  = (const float*)d_in[13];
    const float* bd  = (const float*)d_in[14];

    float *Zb, *Ha, *Hb;
    cudaGetSymbolAddress((void**)&Zb, g_z);
    cudaGetSymbolAddress((void**)&Ha, g_ha);
    cudaGetSymbolAddress((void**)&Hb, g_hb);

    cudaFuncSetAttribute(lstm_scan_h100,
                         cudaFuncAttributeMaxDynamicSharedMemorySize, S1_SMEM);

    // Layer 0: Din=128, H=100
    sgemm_bias<<<dim3(7, M_ROWS / 64), 256>>>(xs, Wx0, b0, Zb, M_ROWS, 400, 128);
    lstm_scan_h100<<<128, 128, S1_SMEM>>>(Zb, Wh0, Ha);
    // Layer 1: Din=100, H=100
    sgemm_bias<<<dim3(7, M_ROWS / 64), 256>>>(Ha, Wx1, b1, Zb, M_ROWS, 400, 100);
    lstm_scan_h100<<<128, 128, S1_SMEM>>>(Zb, Wh1, Hb);
    // Layer 2: Din=100, H=200
    sgemm_bias<<<dim3(13, M_ROWS / 64), 256>>>(Hb, Wx2, b2, Zb, M_ROWS, 800, 100);
    launch_scan_big(Zb, Wh2, Ha);
    // Layer 3: Din=200, H=200
    sgemm_bias<<<dim3(13, M_ROWS / 64), 256>>>(Ha, Wx3, b3, Zb, M_ROWS, 800, 200);
    launch_scan_big(Zb, Wh3, Hb);
    // Dense head
    dense_out<<<3, 256>>>(Hb, Wd, bd, (float*)d_out);
}

// round 2
// speedup vs baseline: 1.3350x; 1.3350x over previous
#include <cuda_runtime.h>
#include <cstdint>
#include <cstddef>

#define T_STEPS 1024
#define BATCH   128
#define M_ROWS  (BATCH * T_STEPS)   // 131072

// Scratch (allocation-free rule: __device__ globals)
__device__ float g_z[104857600];   // [131072, 800] max
__device__ float g_ha[26214400];   // [131072, 200] max
__device__ float g_hb[26214400];   // [131072, 200] max

// ---------------------------------------------------------------- helpers
__device__ __forceinline__ float fast_tanh(float x) {
    float y;
    asm("tanh.approx.f32 %0, %1;" : "=f"(y) : "f"(x));
    return y;
}
__device__ __forceinline__ float fast_sig(float x) {
    return fmaf(fast_tanh(0.5f * x), 0.5f, 0.5f);
}
__device__ __forceinline__ unsigned long long fma2(
    unsigned long long a, unsigned long long b, unsigned long long c) {
    unsigned long long d;
    asm("fma.rn.f32x2 %0, %1, %2, %3;" : "=l"(d) : "l"(a), "l"(b), "l"(c));
    return d;
}
__device__ __forceinline__ float lo32(unsigned long long v) {
    return __uint_as_float((unsigned)v);
}
__device__ __forceinline__ float hi32(unsigned long long v) {
    return __uint_as_float((unsigned)(v >> 32));
}
__device__ __forceinline__ unsigned long long pack2(float lo, float hi) {
    unsigned long long r;
    asm("mov.b64 %0, {%1,%2};" : "=l"(r) : "f"(lo), "f"(hi));
    return r;
}
__device__ __forceinline__ uint32_t smem_u32(const void* p) {
    uint32_t a;
    asm("{ .reg .u64 t; cvta.to.shared.u64 t, %1; cvt.u32.u64 %0, t; }" : "=r"(a) : "l"(p));
    return a;
}

// ---------------------------------------------------------------- GEMM
// C[M,N] = A[M,K] @ B[K,N] + bias.  BM=128, BN=64, BK=16, 256 thr,
// 8m x 4n per thread, m packed in f32x2, B duplicated in smem.
__global__ __launch_bounds__(256, 2) void sgemm_bias(
    const float* __restrict__ A, const float* __restrict__ B,
    const float* __restrict__ bias, float* __restrict__ C,
    int M, int N, int K)
{
    __shared__ float As[16][132];     // [k][m]
    __shared__ float Bd0[16][72];     // dup pairs for j0,j1
    __shared__ float Bd1[16][72];     // dup pairs for j2,j3

    const int tid = threadIdx.x;
    const int tx = tid & 15, ty = tid >> 4;
    const int m0 = blockIdx.y * 128, n0 = blockIdx.x * 64;
    const int a_k = tid & 15, a_m = tid >> 4;
    const int b_n = tid & 63, b_k = tid >> 6;
    const int br = b_n & 3, bb = (b_n >> 2) * 4;

    unsigned long long acc[4][4];
#pragma unroll
    for (int i = 0; i < 4; i++)
#pragma unroll
        for (int j = 0; j < 4; j++) acc[i][j] = 0ull;

    for (int k0 = 0; k0 < K; k0 += 16) {
        const int kk_a = k0 + a_k;
        const bool ka_ok = kk_a < K;
#pragma unroll
        for (int i = 0; i < 8; i++) {
            int m = a_m + 16 * i;
            As[a_k][m] = ka_ok ? A[(size_t)(m0 + m) * K + kk_a] : 0.f;
        }
#pragma unroll
        for (int i = 0; i < 4; i++) {
            int kk = b_k + 4 * i;
            int gk = k0 + kk, gn = n0 + b_n;
            float v = (gk < K && gn < N) ? B[(size_t)gk * N + gn] : 0.f;
            if (br == 0)      { Bd0[kk][bb + 0] = v; Bd0[kk][bb + 1] = v; }
            else if (br == 1) { Bd0[kk][bb + 2] = v; Bd0[kk][bb + 3] = v; }
            else if (br == 2) { Bd1[kk][bb + 0] = v; Bd1[kk][bb + 1] = v; }
            else              { Bd1[kk][bb + 2] = v; Bd1[kk][bb + 3] = v; }
        }
        __syncthreads();
#pragma unroll
        for (int kk = 0; kk < 16; kk++) {
            ulonglong2 aA = *(const ulonglong2*)&As[kk][ty * 8];
            ulonglong2 aB = *(const ulonglong2*)&As[kk][ty * 8 + 4];
            ulonglong2 b0 = *(const ulonglong2*)&Bd0[kk][tx * 4];
            ulonglong2 b1 = *(const ulonglong2*)&Bd1[kk][tx * 4];
            acc[0][0] = fma2(aA.x, b0.x, acc[0][0]);
            acc[1][0] = fma2(aA.y, b0.x, acc[1][0]);
            acc[2][0] = fma2(aB.x, b0.x, acc[2][0]);
            acc[3][0] = fma2(aB.y, b0.x, acc[3][0]);
            acc[0][1] = fma2(aA.x, b0.y, acc[0][1]);
            acc[1][1] = fma2(aA.y, b0.y, acc[1][1]);
            acc[2][1] = fma2(aB.x, b0.y, acc[2][1]);
            acc[3][1] = fma2(aB.y, b0.y, acc[3][1]);
            acc[0][2] = fma2(aA.x, b1.x, acc[0][2]);
            acc[1][2] = fma2(aA.y, b1.x, acc[1][2]);
            acc[2][2] = fma2(aB.x, b1.x, acc[2][2]);
            acc[3][2] = fma2(aB.y, b1.x, acc[3][2]);
            acc[0][3] = fma2(aA.x, b1.y, acc[0][3]);
            acc[1][3] = fma2(aA.y, b1.y, acc[1][3]);
            acc[2][3] = fma2(aB.x, b1.y, acc[2][3]);
            acc[3][3] = fma2(aB.y, b1.y, acc[3][3]);
        }
        __syncthreads();
    }

    const int nb = n0 + tx * 4;
    float bi[4];
#pragma unroll
    for (int j = 0; j < 4; j++) bi[j] = (nb + j < N) ? bias[nb + j] : 0.f;
#pragma unroll
    for (int mp = 0; mp < 4; mp++) {
        int m_lo = m0 + ty * 8 + 2 * mp;
#pragma unroll
        for (int e = 0; e < 2; e++) {
            float v0 = (e ? hi32(acc[mp][0]) : lo32(acc[mp][0])) + bi[0];
            float v1 = (e ? hi32(acc[mp][1]) : lo32(acc[mp][1])) + bi[1];
            float v2 = (e ? hi32(acc[mp][2]) : lo32(acc[mp][2])) + bi[2];
            float v3 = (e ? hi32(acc[mp][3]) : lo32(acc[mp][3])) + bi[3];
            float* cp = C + (size_t)(m_lo + e) * N + nb;
            if (nb + 3 < N) {
                *(float4*)cp = make_float4(v0, v1, v2, v3);
            } else {
                if (nb + 0 < N) cp[0] = v0;
                if (nb + 1 < N) cp[1] = v1;
                if (nb + 2 < N) cp[2] = v2;
                if (nb + 3 < N) cp[3] = v3;
            }
        }
    }
}

// ---------------------------------------------------------------- scan H=100
// 128 CTAs x 416 thr. Threads 0..399: gate-column tid, weights (100 fp32 as
// 50 f32x2) in REGISTERS. Per step: dot vs broadcast h (LDS.128), activation
// to smem, then threads <100 do the c/h update.
__global__ __launch_bounds__(416, 1) void lstm_scan_h100(
    const float* __restrict__ Z, const float* __restrict__ Wh,
    float* __restrict__ Hout)
{
    __shared__ float hb[2][104];
    __shared__ float gact[400];

    const int tid = threadIdx.x;
    const int row = blockIdx.x;
    const bool dotw = tid < 400;
    const bool isG = (tid >= 200 && tid < 300);

    unsigned long long w[50];
#pragma unroll
    for (int q = 0; q < 50; q++) {
        float wlo = 0.f, whi = 0.f;
        if (dotw) {
            wlo = Wh[(size_t)(2 * q) * 400 + tid];
            whi = Wh[(size_t)(2 * q + 1) * 400 + tid];
        }
        w[q] = pack2(wlo, whi);
    }
    if (tid < 104) { hb[0][tid] = 0.f; hb[1][tid] = 0.f; }
    __syncthreads();

    const float* Zr = Z + (size_t)row * T_STEPS * 400;
    float* Ho = Hout + (size_t)row * T_STEPS * 100;
    float c = 0.f;
    float zc = dotw ? Zr[tid] : 0.f;
    int cur = 0;

    for (int t = 0; t < T_STEPS; t++) {
        float zn = 0.f;
        if (dotw) {
            int tn = (t + 1 < T_STEPS) ? t + 1 : t;
            zn = Zr[(size_t)tn * 400 + tid];
        }
        unsigned long long a0 = 0ull, a1 = 0ull;
        const ulonglong2* hp = (const ulonglong2*)&hb[cur][0];
#pragma unroll
        for (int q = 0; q < 25; q++) {
            ulonglong2 h2 = hp[q];
            a0 = fma2(w[2 * q], h2.x, a0);
            a1 = fma2(w[2 * q + 1], h2.y, a1);
        }
        if (dotw) {
            float pre = zc + lo32(a0) + hi32(a0) + lo32(a1) + hi32(a1);
            gact[tid] = isG ? fast_tanh(pre) : fast_sig(pre);
        }
        __syncthreads();
        int nxt = cur ^ 1;
        if (tid < 104) {
            float hnew = 0.f;
            if (tid < 100) {
                float gi = gact[tid], gf = gact[100 + tid];
                float gg = gact[200 + tid], go = gact[300 + tid];
                c = fmaf(gf, c, gi * gg);
                hnew = go * fast_tanh(c);
                Ho[(size_t)t * 100 + tid] = hnew;
            }
            hb[nxt][tid] = hnew;
        }
        __syncthreads();
        zc = zn;
        cur = nxt;
    }
}

// ---------------------------------------------------------------- scan H=200
// Cluster of 4 CTAs = 4 batch rows; CTA rank rk owns hidden slice
// [50rk,50rk+50) x 4 gates. Weights in REGISTERS: threads 0..399 own
// (local col = tid/2, K-half = tid&1): 100 fp32 = 50 f32x2 regs, computing
// dots for all 4 rows. Halves merged via shfl.down 1 (adjacent lanes).
__global__ __launch_bounds__(416, 1) void lstm_scan_h200(
    const float* __restrict__ Z, const float* __restrict__ Wh,
    float* __restrict__ Hout, int writeAll)
{
    __shared__ float hb[2][4][200];
    __shared__ float gact[4][200];   // [row][gate*50+mm]

    const int tid = threadIdx.x;
    uint32_t rk;
    asm("mov.u32 %0, %%cluster_ctarank;" : "=r"(rk));
    const bool dotw = tid < 400;
    const int lc = tid >> 1;          // 0..199 (local col: gate*50+mm)
    const int half = tid & 1;
    const int g = lc / 50, mm = lc - g * 50;
    const int gcol = g * 200 + (int)rk * 50 + mm;   // column in 800-wide z

    unsigned long long w[50];
#pragma unroll
    for (int q = 0; q < 50; q++) {
        float wlo = 0.f, whi = 0.f;
        if (dotw) {
            int k = half * 100 + 2 * q;
            wlo = Wh[(size_t)k * 800 + gcol];
            whi = Wh[(size_t)(k + 1) * 800 + gcol];
        }
        w[q] = pack2(wlo, whi);
    }
    for (int i = tid; i < 2 * 4 * 200; i += 416) ((float*)hb)[i] = 0.f;
    __syncthreads();
    asm volatile("barrier.cluster.arrive.aligned;" ::: "memory");
    asm volatile("barrier.cluster.wait.aligned;" ::: "memory");

    const int b0 = (blockIdx.x >> 2) * 4;
    const int ur = (tid < 200) ? tid / 50 : 0;     // update role
    const int um = (tid < 200) ? tid % 50 : 0;
    const int ugm = (int)rk * 50 + um;
    float c = 0.f;

    const size_t zstride = (size_t)T_STEPS * 800;
    const float* Zbase = Z + (size_t)b0 * zstride + gcol;
    float zc0 = 0.f, zc1 = 0.f, zc2 = 0.f, zc3 = 0.f;
    if (dotw && half == 0) {
        zc0 = Zbase[0];
        zc1 = Zbase[zstride];
        zc2 = Zbase[2 * zstride];
        zc3 = Zbase[3 * zstride];
    }
    const uint32_t hbB = smem_u32(&hb[0][0][0]);
    int cur = 0;

    for (int t = 0; t < T_STEPS; t++) {
        float zn0 = 0.f, zn1 = 0.f, zn2 = 0.f, zn3 = 0.f;
        if (dotw && half == 0) {
            size_t off = (size_t)((t + 1 < T_STEPS) ? t + 1 : t) * 800;
            zn0 = Zbase[off];
            zn1 = Zbase[zstride + off];
            zn2 = Zbase[2 * zstride + off];
            zn3 = Zbase[3 * zstride + off];
        }
        unsigned long long a0 = 0ull, a1 = 0ull, a2 = 0ull, a3 = 0ull;
        {
            const ulonglong2* hp0 = (const ulonglong2*)&hb[cur][0][half * 100];
            const ulonglong2* hp1 = (const ulonglong2*)&hb[cur][1][half * 100];
            const ulonglong2* hp2 = (const ulonglong2*)&hb[cur][2][half * 100];
            const ulonglong2* hp3 = (const ulonglong2*)&hb[cur][3][half * 100];
#pragma unroll
            for (int q = 0; q < 25; q++) {
                ulonglong2 h0 = hp0[q];
                ulonglong2 h1 = hp1[q];
                ulonglong2 h2 = hp2[q];
                ulonglong2 h3 = hp3[q];
                a0 = fma2(w[2 * q], h0.x, a0);
                a1 = fma2(w[2 * q], h1.x, a1);
                a2 = fma2(w[2 * q], h2.x, a2);
                a3 = fma2(w[2 * q], h3.x, a3);
                a0 = fma2(w[2 * q + 1], h0.y, a0);
                a1 = fma2(w[2 * q + 1], h1.y, a1);
                a2 = fma2(w[2 * q + 1], h2.y, a2);
                a3 = fma2(w[2 * q + 1], h3.y, a3);
            }
        }
        float s0 = lo32(a0) + hi32(a0);
        float s1 = lo32(a1) + hi32(a1);
        float s2 = lo32(a2) + hi32(a2);
        float s3 = lo32(a3) + hi32(a3);
        // merge K-halves: odd lane -> even lane (unconditional, full warps)
        float p0 = __shfl_down_sync(0xFFFFFFFFu, s0, 1);
        float p1 = __shfl_down_sync(0xFFFFFFFFu, s1, 1);
        float p2 = __shfl_down_sync(0xFFFFFFFFu, s2, 1);
        float p3 = __shfl_down_sync(0xFFFFFFFFu, s3, 1);
        if (dotw && half == 0) {
            float pre0 = zc0 + s0 + p0;
            float pre1 = zc1 + s1 + p1;
            float pre2 = zc2 + s2 + p2;
            float pre3 = zc3 + s3 + p3;
            if (g == 2) {
                gact[0][lc] = fast_tanh(pre0);
                gact[1][lc] = fast_tanh(pre1);
                gact[2][lc] = fast_tanh(pre2);
                gact[3][lc] = fast_tanh(pre3);
            } else {
                gact[0][lc] = fast_sig(pre0);
                gact[1][lc] = fast_sig(pre1);
                gact[2][lc] = fast_sig(pre2);
                gact[3][lc] = fast_sig(pre3);
            }
        }
        __syncthreads();
        int nxt = cur ^ 1;
        if (tid < 200) {
            float gi = gact[ur][um];
            float gf = gact[ur][50 + um];
            float gg = gact[ur][100 + um];
            float go = gact[ur][150 + um];
            c = fmaf(gf, c, gi * gg);
            float hnew = go * fast_tanh(c);
            if (writeAll || t == T_STEPS - 1)
                Hout[((size_t)(b0 + ur) * T_STEPS + t) * 200 + ugm] = hnew;
            uint32_t loff = hbB + (uint32_t)(((nxt * 4 + ur) * 200 + ugm) * 4);
#pragma unroll
            for (uint32_t j = 0; j < 4; j++) {
                uint32_t pa;
                asm("mapa.shared::cluster.u32 %0, %1, %2;" : "=r"(pa) : "r"(loff), "r"(j));
                asm volatile("st.shared::cluster.f32 [%0], %1;" :: "r"(pa), "f"(hnew) : "memory");
            }
        }
        asm volatile("barrier.cluster.arrive.aligned;" ::: "memory");
        asm volatile("barrier.cluster.wait.aligned;" ::: "memory");
        zc0 = zn0; zc1 = zn1; zc2 = zn2; zc3 = zn3;
        cur = nxt;
    }
}

// ---------------------------------------------------------------- dense out
__global__ __launch_bounds__(256) void dense_out(
    const float* __restrict__ Hlast, const float* __restrict__ Wd,
    const float* __restrict__ bd, float* __restrict__ out)
{
    int p = blockIdx.x * blockDim.x + threadIdx.x;
    if (p >= BATCH * 6) return;
    int b = p / 6, o = p - b * 6;
    const float* h = Hlast + ((size_t)b * T_STEPS + (T_STEPS - 1)) * 200;
    float s = bd[o];
#pragma unroll 4
    for (int k = 0; k < 200; k++) s = fmaf(h[k], Wd[k * 6 + o], s);
    out[p] = s;
}

// ---------------------------------------------------------------- launch
static void launch_scan_big(const float* Z, const float* Wh, float* Hout,
                            int writeAll)
{
    cudaLaunchConfig_t cfg = {};
    cfg.gridDim = dim3(128, 1, 1);
    cfg.blockDim = dim3(416, 1, 1);
    cfg.dynamicSmemBytes = 0;
    cfg.stream = 0;
    cudaLaunchAttribute attrs[1];
    attrs[0].id = cudaLaunchAttributeClusterDimension;
    attrs[0].val.clusterDim.x = 4;
    attrs[0].val.clusterDim.y = 1;
    attrs[0].val.clusterDim.z = 1;
    cfg.attrs = attrs;
    cfg.numAttrs = 1;
    cudaLaunchKernelEx(&cfg, lstm_scan_h200, Z, Wh, Hout, writeAll);
}

extern "C" void kernel_launch(void* const* d_in, const int* in_sizes, int n_in,
                              void* d_out, int out_size)
{
    const float* xs  = (const float*)d_in[0];
    const float* Wx0 = (const float*)d_in[1];
    const float* Wh0 = (const float*)d_in[2];
    const float* b0  = (const float*)d_in[3];
    const float* Wx1 = (const float*)d_in[4];
    const float* Wh1 = (const float*)d_in[5];
    const float* b1  = (const float*)d_in[6];
    const float* Wx2 = (const float*)d_in[7];
    const float* Wh2 = (const float*)d_in[8];
    const float* b2  = (const float*)d_in[9];
    const float* Wx3 = (const float*)d_in[10];
    const float* Wh3 = (const float*)d_in[11];
    const float* b3  = (const float*)d_in[12];
    const float* Wd  = (const float*)d_in[13];
    const float* bd  = (const float*)d_in[14];

    float *Zb, *Ha, *Hb;
    cudaGetSymbolAddress((void**)&Zb, g_z);
    cudaGetSymbolAddress((void**)&Ha, g_ha);
    cudaGetSymbolAddress((void**)&Hb, g_hb);

    // Layer 0: Din=128, H=100
    sgemm_bias<<<dim3(7, M_ROWS / 128), 256>>>(xs, Wx0, b0, Zb, M_ROWS, 400, 128);
    lstm_scan_h100<<<128, 416>>>(Zb, Wh0, Ha);
    // Layer 1: Din=100, H=100
    sgemm_bias<<<dim3(7, M_ROWS / 128), 256>>>(Ha, Wx1, b1, Zb, M_ROWS, 400, 100);
    lstm_scan_h100<<<128, 416>>>(Zb, Wh1, Hb);
    // Layer 2: Din=100, H=200
    sgemm_bias<<<dim3(13, M_ROWS / 128), 256>>>(Hb, Wx2, b2, Zb, M_ROWS, 800, 100);
    launch_scan_big(Zb, Wh2, Ha, 1);
    // Layer 3: Din=200, H=200 (only last h needed downstream)
    sgemm_bias<<<dim3(13, M_ROWS / 128), 256>>>(Ha, Wx3, b3, Zb, M_ROWS, 800, 200);
    launch_scan_big(Zb, Wh3, Hb, 0);
    // Dense head
    dense_out<<<3, 256>>>(Hb, Wd, bd, (float*)d_out);
}